// round 12
// baseline (speedup 1.0000x reference)
#include <cuda_runtime.h>
#include <cuda_fp16.h>
#include <math.h>
#include <stdint.h>

#define Bdim 8
#define Vn   256
#define Hn   128
#define NR   2048      /* B*V   */
#define NE   524288    /* B*V*V */

// ---------------- device scratch (no allocation allowed) ----------------
__device__ float g_Uh[NR * Hn];
__device__ float g_Vh[NR * Hn];
__device__ float g_Ah[NR * Hn];
__device__ float g_Bh[NR * Hn];
__device__ float g_hnew[NR * Hn];
__device__ float g_esum[Hn];
__device__ float g_esq[Hn];
__device__ float2 g_Wp[64 * 128];            // paired tf32 Cw: [(k>>3)*4+(k&3)][n] = (k, k+4)
__device__ __half g_enew[(size_t)NE * Hn];   // 134 MB fp16 spill of e_new

// ---------------- helpers ----------------
__device__ __forceinline__ unsigned smem_u32(const void* p) {
    unsigned a;
    asm("{ .reg .u64 t; cvta.to.shared.u64 t, %1; cvt.u32.u64 %0, t; }"
        : "=r"(a) : "l"(p));
    return a;
}
__device__ __forceinline__ void cp_async16(unsigned dst, const void* src) {
    asm volatile("cp.async.cg.shared.global [%0], [%1], 16;\n" :: "r"(dst), "l"(src));
}
__device__ __forceinline__ uint32_t f2tf32(float f) {
    uint32_t u;
    asm("cvt.rna.tf32.f32 %0, %1;" : "=r"(u) : "f"(f));
    return u;
}
__device__ __forceinline__ float fast_sigmoid(float x) {
    float t;
    asm("tanh.approx.f32 %0, %1;" : "=f"(t) : "f"(0.5f * x));
    return 0.5f * t + 0.5f;
}

// ---------------- kernels ----------------

// two h-linears per launch; which==0 also zeroes BN accumulators and builds
// the paired-tf32 W copy for pass1 (blocks 0..7 handle 2048 entries each).
#define HL_STR 132
__global__ __launch_bounds__(256)
void k_hlin2(const float* __restrict__ h,
             const float* __restrict__ W1, const float* __restrict__ b1,
             const float* __restrict__ W2, const float* __restrict__ b2,
             const float* __restrict__ Cw,
             int which) {
    __shared__ float hs[16 * HL_STR];
    __shared__ float Ws[128 * HL_STR];
    const int t = threadIdx.x;
    const int lane = t & 31, wq = t >> 5;
    const int rbase = blockIdx.x * 16;
    if (which == 0) {
        if (blockIdx.x == 0 && t < Hn) { g_esum[t] = 0.f; g_esq[t] = 0.f; }
        if (blockIdx.x < 8) {
            uint32_t* WpU = (uint32_t*)g_Wp;
#pragma unroll
            for (int r = 0; r < 8; r++) {
                int i = blockIdx.x * 2048 + r * 256 + t;
                int n = i >> 7, k = i & 127;
                int kp = (k >> 3) * 4 + (k & 3), sel = (k >> 2) & 1;
                WpU[(kp * 128 + n) * 2 + sel] = f2tf32(Cw[i]);
            }
        }
    }
    {
        int idx0 = t, idx1 = t + 256;
        int r0 = idx0 >> 5, kq0 = idx0 & 31;
        int r1 = idx1 >> 5, kq1 = idx1 & 31;
        *(float4*)(hs + r0 * HL_STR + kq0 * 4) = *(const float4*)(h + (size_t)(rbase + r0) * Hn + kq0 * 4);
        *(float4*)(hs + r1 * HL_STR + kq1 * 4) = *(const float4*)(h + (size_t)(rbase + r1) * Hn + kq1 * 4);
    }
    const float* Wp[2]; const float* bp[2]; float* Op[2];
    Wp[0] = W1; Wp[1] = W2; bp[0] = b1; bp[1] = b2;
    if (which) { Op[0] = g_Ah; Op[1] = g_Bh; } else { Op[0] = g_Uh; Op[1] = g_Vh; }
    const int r0 = wq * 2, r1 = wq * 2 + 1;
    for (int a = 0; a < 2; a++) {
        __syncthreads();
        const float* W = Wp[a];
#pragma unroll
        for (int i = 0; i < 16; i++) {
            int idx = t + i * 256;
            int o = idx >> 5, kq = idx & 31;
            *(float4*)(Ws + o * HL_STR + kq * 4) = *(const float4*)(W + (size_t)o * Hn + kq * 4);
        }
        __syncthreads();
        float acc0[4] = {0.f, 0.f, 0.f, 0.f};
        float acc1[4] = {0.f, 0.f, 0.f, 0.f};
#pragma unroll 4
        for (int k4 = 0; k4 < 32; k4++) {
            float4 h0 = *(const float4*)(hs + r0 * HL_STR + k4 * 4);
            float4 h1 = *(const float4*)(hs + r1 * HL_STR + k4 * 4);
#pragma unroll
            for (int c = 0; c < 4; c++) {
                float4 w = *(const float4*)(Ws + (lane + 32 * c) * HL_STR + k4 * 4);
                acc0[c] += h0.x * w.x + h0.y * w.y + h0.z * w.z + h0.w * w.w;
                acc1[c] += h1.x * w.x + h1.y * w.y + h1.z * w.z + h1.w * w.w;
            }
        }
        float* O = Op[a];
        const float* bb = bp[a];
#pragma unroll
        for (int c = 0; c < 4; c++) {
            int col = lane + 32 * c;
            float bv = bb[col];
            O[(size_t)(rbase + r0) * Hn + col] = acc0[c] + bv;
            O[(size_t)(rbase + r1) * Hn + col] = acc1[c] + bv;
        }
    }
}

// Pass 1: tf32 mma.sync GEMM + coalesced fused epilogue, 2 CTAs/SM,
// 2 independent 4-warp groups per CTA (named barriers), 32-row chunks,
// DOUBLE-BUFFERED staging (chunk c+2 prefetched during c+1's compute).
// B-fragments (paired W) come straight from global g_Wp via LDG (L1-resident).
// e_new spilled as fp16; stats fp32.
#define AS_STRIDE 132
#define BUF_FLOATS 4224               /* 32*132 */
#define GS_OFF    16896               /* 4 buffers */
#define SMEM_FLOATS 17152             /* 68608 B -> 2 CTAs/SM (RF-limited) */
// reduction scratch inside retired buffer area (floats): 8 warps x 132
#define RED_SQ    1056
#define RED_AGG   2112

__global__ __launch_bounds__(256, 2)
void k_pass1(const float* __restrict__ e,
             const int* __restrict__ graph,
             const float* __restrict__ Cb) {
    extern __shared__ float sm[];
    int* gs = (int*)(sm + GS_OFF);

    const int p = blockIdx.x, b = p >> 8;
    const int t = threadIdx.x;
    const int lane = t & 31, wid = t >> 5;
    const int g  = wid >> 2;              // group 0/1
    const int wq = wid & 3;               // warp-in-group = h block
    const int gid = lane >> 2, tig = lane & 3;
    const int barid = g + 1;
    const int gt = t & 127;

    float* buf0 = sm + (g * 2) * BUF_FLOATS;
    float* buf1 = sm + (g * 2 + 1) * BUF_FLOATS;
    const unsigned db0 = smem_u32(buf0);
    const unsigned db1 = smem_u32(buf1);
    const float* ebase = e + (size_t)p * Vn * Hn;

    // prologue: stage chunks c=0 (j0=g*32) and c=1 (j0=(2+g)*32)
#pragma unroll
    for (int i = 0; i < 8; i++) {
        int fid = i * 128 + gt;
        int row = fid >> 5, kq = fid & 31;
        cp_async16(db0 + (row * AS_STRIDE + kq * 4) * 4,
                   ebase + (size_t)(g * 32 + row) * Hn + kq * 4);
    }
    asm volatile("cp.async.commit_group;\n");
#pragma unroll
    for (int i = 0; i < 8; i++) {
        int fid = i * 128 + gt;
        int row = fid >> 5, kq = fid & 31;
        cp_async16(db1 + (row * AS_STRIDE + kq * 4) * 4,
                   ebase + (size_t)((2 + g) * 32 + row) * Hn + kq * 4);
    }
    asm volatile("cp.async.commit_group;\n");

    gs[t] = graph[p * Vn + t];

    const int h4 = lane * 4;
    float4 bias4;
    {
        float4 bb = *(const float4*)(g_Bh + (size_t)p * Hn + h4);
        float4 cb = *(const float4*)(Cb + h4);
        bias4 = make_float4(bb.x + cb.x, bb.y + cb.y, bb.z + cb.z, bb.w + cb.w);
    }
    float4 sum4 = make_float4(0.f, 0.f, 0.f, 0.f);
    float4 sq4  = make_float4(0.f, 0.f, 0.f, 0.f);
    float4 agg4 = make_float4(0.f, 0.f, 0.f, 0.f);

    __syncthreads();    // gs visible

    const uint2* Wg = (const uint2*)g_Wp;
    const float* AhB = g_Ah + (size_t)b * Vn * Hn;
    const float* VhB = g_Vh + (size_t)b * Vn * Hn;

    for (int c = 0; c < 4; c++) {
        const int j0 = (c * 2 + g) * 32;
        float* As = (c & 1) ? buf1 : buf0;
        const uint32_t* AbufU = (const uint32_t*)As;

        if (c < 3) { asm volatile("cp.async.wait_group 1;\n" ::: "memory"); }
        else       { asm volatile("cp.async.wait_group 0;\n" ::: "memory"); }
        asm volatile("bar.sync %0, 128;" :: "r"(barid) : "memory");

        // ---- GEMM: warp tile 32(j) x 32(h) over the 32-row chunk ----
        float cf[2][4][4];
#pragma unroll
        for (int rg = 0; rg < 2; rg++)
#pragma unroll
            for (int nt = 0; nt < 4; nt++)
#pragma unroll
                for (int q = 0; q < 4; q++) cf[rg][nt][q] = 0.f;

#pragma unroll 2
        for (int ks = 0; ks < 16; ks++) {
            int k0 = ks * 8 + tig;
            uint32_t a[2][4];
#pragma unroll
            for (int rg = 0; rg < 2; rg++) {
                int r = rg * 16 + gid;
                a[rg][0] = AbufU[r * AS_STRIDE + k0];
                a[rg][1] = AbufU[(r + 8) * AS_STRIDE + k0];
                a[rg][2] = AbufU[r * AS_STRIDE + k0 + 4];
                a[rg][3] = AbufU[(r + 8) * AS_STRIDE + k0 + 4];
            }
            uint2 bfr[4];
            const uint2* WgK = Wg + (ks * 4 + tig) * 128 + wq * 32 + gid;
#pragma unroll
            for (int nt = 0; nt < 4; nt++)
                bfr[nt] = __ldg(WgK + nt * 8);
#pragma unroll
            for (int rg = 0; rg < 2; rg++)
#pragma unroll
                for (int nt = 0; nt < 4; nt++) {
                    asm volatile(
                        "mma.sync.aligned.m16n8k8.row.col.f32.tf32.tf32.f32 "
                        "{%0,%1,%2,%3},{%4,%5,%6,%7},{%8,%9},{%0,%1,%2,%3};"
                        : "+f"(cf[rg][nt][0]), "+f"(cf[rg][nt][1]),
                          "+f"(cf[rg][nt][2]), "+f"(cf[rg][nt][3])
                        : "r"(a[rg][0]), "r"(a[rg][1]), "r"(a[rg][2]), "r"(a[rg][3]),
                          "r"(bfr[nt].x), "r"(bfr[nt].y));
                }
        }

        asm volatile("bar.sync %0, 128;" :: "r"(barid) : "memory");
        // ---- transpose fragments into the (now dead) staging buffer ----
#pragma unroll
        for (int rg = 0; rg < 2; rg++)
#pragma unroll
            for (int half = 0; half < 2; half++) {
                int jl = rg * 16 + half * 8 + gid;
#pragma unroll
                for (int nt = 0; nt < 4; nt++) {
                    int h = wq * 32 + nt * 8 + tig * 2;
                    *(float2*)(As + jl * AS_STRIDE + h) =
                        make_float2(cf[rg][nt][half * 2], cf[rg][nt][half * 2 + 1]);
                }
            }
        asm volatile("bar.sync %0, 128;" :: "r"(barid) : "memory");

        // ---- coalesced epilogue: warp owns rows [wq*8, wq*8+8) of chunk ----
#pragma unroll
        for (int r = 0; r < 8; r++) {
            int jl = wq * 8 + r;
            int j  = j0 + jl;
            float4 cv = *(const float4*)(As + jl * AS_STRIDE + h4);
            float4 ah = *(const float4*)(AhB + (size_t)j * Hn + h4);
            float4 en;
            en.x = cv.x + ah.x + bias4.x;
            en.y = cv.y + ah.y + bias4.y;
            en.z = cv.z + ah.z + bias4.z;
            en.w = cv.w + ah.w + bias4.w;
            {
                __half2 ha = __floats2half2_rn(en.x, en.y);
                __half2 hb = __floats2half2_rn(en.z, en.w);
                uint2 pk;
                pk.x = *(uint32_t*)&ha;
                pk.y = *(uint32_t*)&hb;
                __stcs((uint2*)(g_enew + ((size_t)p * Vn + j) * Hn) + lane, pk);
            }
            sum4.x += en.x; sum4.y += en.y; sum4.z += en.z; sum4.w += en.w;
            sq4.x += en.x * en.x; sq4.y += en.y * en.y;
            sq4.z += en.z * en.z; sq4.w += en.w * en.w;
            if (!gs[j]) {
                float4 vh = *(const float4*)(VhB + (size_t)j * Hn + h4);
                agg4.x += fast_sigmoid(en.x) * vh.x;
                agg4.y += fast_sigmoid(en.y) * vh.y;
                agg4.z += fast_sigmoid(en.z) * vh.z;
                agg4.w += fast_sigmoid(en.w) * vh.w;
            }
        }
        asm volatile("bar.sync %0, 128;" :: "r"(barid) : "memory");

        // ---- prefetch chunk c+2 into the buffer just consumed ----
        if (c < 2) {
            int jn = ((c + 2) * 2 + g) * 32;
            unsigned db = (c & 1) ? db1 : db0;
#pragma unroll
            for (int i = 0; i < 8; i++) {
                int fid = i * 128 + gt;
                int row = fid >> 5, kq = fid & 31;
                cp_async16(db + (row * AS_STRIDE + kq * 4) * 4,
                           ebase + (size_t)(jn + row) * Hn + kq * 4);
            }
            asm volatile("cp.async.commit_group;\n");
        }
    }

    // ---- block reduction via retired buffer area ----
    float* redS = sm;
    __syncthreads();
    *(float4*)(redS + wid * AS_STRIDE + h4)           = sum4;
    *(float4*)(redS + RED_SQ + wid * AS_STRIDE + h4)  = sq4;
    *(float4*)(redS + RED_AGG + wid * AS_STRIDE + h4) = agg4;
    __syncthreads();
    if (t < Hn) {
        float s = 0.f, q = 0.f, gg = 0.f;
#pragma unroll
        for (int w = 0; w < 8; w++) {
            s  += redS[w * AS_STRIDE + t];
            q  += redS[RED_SQ + w * AS_STRIDE + t];
            gg += redS[RED_AGG + w * AS_STRIDE + t];
        }
        atomicAdd(&g_esum[t], s);
        atomicAdd(&g_esq[t],  q);
        g_hnew[(size_t)p * Hn + t] = g_Uh[(size_t)p * Hn + t] + gg;
    }
}

// pass 2 over e: normalize + relu + residual (blocks < 65536), h-side
// batchnorm as tail blocks. BN scale/shift derived in-block from g_esum/g_esq.
__global__ void k_epass2(const float* __restrict__ ein,
                         float* __restrict__ eout,
                         const float* __restrict__ game,
                         const float* __restrict__ bete,
                         const float* __restrict__ hin,
                         const float* __restrict__ gamh,
                         const float* __restrict__ beth,
                         float* __restrict__ hout) {
    if (blockIdx.x < 65536) {
        __shared__ float scS[128], shS[128];
        int t = threadIdx.x;
        if (t < 128) {
            float mean = g_esum[t] * (1.0f / NE);
            float var  = g_esq[t] * (1.0f / NE) - mean * mean;
            float sc = game[t] * rsqrtf(var + 1e-5f);
            scS[t] = sc;
            shS[t] = bete[t] - mean * sc;
        }
        __syncthreads();
        size_t idx = (size_t)blockIdx.x * blockDim.x + t;   // 4-channel unit idx
        int h0 = (int)((idx * 4) & 127);
        uint2 pk = __ldcs((const uint2*)g_enew + idx);
        __half2 ha = *(__half2*)&pk.x;
        __half2 hb = *(__half2*)&pk.y;
        float2 f01 = __half22float2(ha);
        float2 f23 = __half22float2(hb);
        float4 a = __ldcs((const float4*)ein + idx);
        float4 o;
        o.x = a.x + fmaxf(f01.x * scS[h0]     + shS[h0],     0.f);
        o.y = a.y + fmaxf(f01.y * scS[h0 + 1] + shS[h0 + 1], 0.f);
        o.z = a.z + fmaxf(f23.x * scS[h0 + 2] + shS[h0 + 2], 0.f);
        o.w = a.w + fmaxf(f23.y * scS[h0 + 3] + shS[h0 + 3], 0.f);
        ((float4*)eout)[idx] = o;
    } else {
        int h = blockIdx.x - 65536, t = threadIdx.x;
        float v[8];
        float s = 0.f, q = 0.f;
#pragma unroll
        for (int r = 0; r < 8; r++) {
            float x = g_hnew[(size_t)(t * 8 + r) * Hn + h];
            v[r] = x; s += x; q += x * x;
        }
        __shared__ float rs[256], rq[256];
        rs[t] = s; rq[t] = q; __syncthreads();
        for (int o = 128; o > 0; o >>= 1) {
            if (t < o) { rs[t] += rs[t + o]; rq[t] += rq[t + o]; }
            __syncthreads();
        }
        __shared__ float sc, sh;
        if (t == 0) {
            float mean = rs[0] * (1.0f / NR);
            float var  = rq[0] * (1.0f / NR) - mean * mean;
            float scale = gamh[h] * rsqrtf(var + 1e-5f);
            sc = scale; sh = beth[h] - mean * scale;
        }
        __syncthreads();
#pragma unroll
        for (int r = 0; r < 8; r++) {
            int row = t * 8 + r;
            float y = fmaxf(v[r] * sc + sh, 0.f);
            hout[(size_t)row * Hn + h] = hin[(size_t)row * Hn + h] + y;
        }
    }
}

// ---------------- launch ----------------
extern "C" void kernel_launch(void* const* d_in, const int* in_sizes, int n_in,
                              void* d_out, int out_size) {
    const float* h   = (const float*)d_in[0];
    const float* e   = (const float*)d_in[1];
    const int*   gra = (const int*)  d_in[2];
    const float* Uw  = (const float*)d_in[3],  *Ub = (const float*)d_in[4];
    const float* Vw  = (const float*)d_in[5],  *Vb = (const float*)d_in[6];
    const float* Aw  = (const float*)d_in[7],  *Ab = (const float*)d_in[8];
    const float* Bw  = (const float*)d_in[9],  *Bb = (const float*)d_in[10];
    const float* Cw  = (const float*)d_in[11], *Cb = (const float*)d_in[12];
    const float* gh  = (const float*)d_in[13], *bh = (const float*)d_in[14];
    const float* ge  = (const float*)d_in[15], *be = (const float*)d_in[16];

    float* out  = (float*)d_out;
    float* hout = out;                        // [2048,128]
    float* eout = out + (size_t)NR * Hn;      // [8,256,256,128]

    const int smemE = SMEM_FLOATS * 4;        // 68608 B
    cudaFuncSetAttribute(k_pass1, cudaFuncAttributeMaxDynamicSharedMemorySize, smemE);

    k_hlin2 <<<128, 256>>>(h, Uw, Ub, Vw, Vb, Cw, 0);   // also zeroes BN accum + builds g_Wp
    k_hlin2 <<<128, 256>>>(h, Aw, Ab, Bw, Bb, Cw, 1);
    k_pass1 <<<NR, 256, smemE>>>(e, gra, Cb);
    k_epass2<<<65664, 256>>>(e, eout, ge, be, h, gh, bh, hout);
}

// round 13
// speedup vs baseline: 1.1471x; 1.1471x over previous
#include <cuda_runtime.h>
#include <cuda_fp16.h>
#include <math.h>
#include <stdint.h>

#define Bdim 8
#define Vn   256
#define Hn   128
#define NR   2048      /* B*V   */
#define NE   524288    /* B*V*V */

// ---------------- device scratch (no allocation allowed) ----------------
__device__ float g_Uh[NR * Hn];
__device__ float g_Vh[NR * Hn];
__device__ float g_Ah[NR * Hn];
__device__ float g_Bh[NR * Hn];
__device__ float g_hnew[NR * Hn];
__device__ float g_esum[Hn];
__device__ float g_esq[Hn];
__device__ __half g_enew[(size_t)NE * Hn];   // 134 MB fp16 spill of e_new

// ---------------- helpers ----------------
__device__ __forceinline__ unsigned smem_u32(const void* p) {
    unsigned a;
    asm("{ .reg .u64 t; cvta.to.shared.u64 t, %1; cvt.u32.u64 %0, t; }"
        : "=r"(a) : "l"(p));
    return a;
}
__device__ __forceinline__ void cp_async16(unsigned dst, const void* src) {
    asm volatile("cp.async.cg.shared.global [%0], [%1], 16;\n" :: "r"(dst), "l"(src));
}
__device__ __forceinline__ uint32_t f2tf32(float f) {
    uint32_t u;
    asm("cvt.rna.tf32.f32 %0, %1;" : "=r"(u) : "f"(f));
    return u;
}
__device__ __forceinline__ float fast_sigmoid(float x) {
    float t;
    asm("tanh.approx.f32 %0, %1;" : "=f"(t) : "f"(0.5f * x));
    return 0.5f * t + 0.5f;
}

// ---------------- kernels ----------------

// all four h-linears in ONE launch: blocks 0..127 -> U/V, 128..255 -> A/B.
// block 0 also zeroes the BN accumulators.
#define HL_STR 132
__global__ __launch_bounds__(256)
void k_hlin4(const float* __restrict__ h,
             const float* __restrict__ Uw, const float* __restrict__ Ub,
             const float* __restrict__ Vw, const float* __restrict__ Vb,
             const float* __restrict__ Aw, const float* __restrict__ Ab,
             const float* __restrict__ Bw, const float* __restrict__ Bb) {
    __shared__ float hs[16 * HL_STR];
    __shared__ float Ws[128 * HL_STR];
    const int t = threadIdx.x;
    const int lane = t & 31, wq = t >> 5;
    const int which = blockIdx.x >> 7;
    const int rbase = (blockIdx.x & 127) * 16;
    if (blockIdx.x == 0 && t < Hn) { g_esum[t] = 0.f; g_esq[t] = 0.f; }
    {
        int idx0 = t, idx1 = t + 256;
        int r0 = idx0 >> 5, kq0 = idx0 & 31;
        int r1 = idx1 >> 5, kq1 = idx1 & 31;
        *(float4*)(hs + r0 * HL_STR + kq0 * 4) = *(const float4*)(h + (size_t)(rbase + r0) * Hn + kq0 * 4);
        *(float4*)(hs + r1 * HL_STR + kq1 * 4) = *(const float4*)(h + (size_t)(rbase + r1) * Hn + kq1 * 4);
    }
    const float* Wp[2]; const float* bp[2]; float* Op[2];
    if (which) { Wp[0] = Aw; Wp[1] = Bw; bp[0] = Ab; bp[1] = Bb; Op[0] = g_Ah; Op[1] = g_Bh; }
    else       { Wp[0] = Uw; Wp[1] = Vw; bp[0] = Ub; bp[1] = Vb; Op[0] = g_Uh; Op[1] = g_Vh; }
    const int r0 = wq * 2, r1 = wq * 2 + 1;
    for (int a = 0; a < 2; a++) {
        __syncthreads();
        const float* W = Wp[a];
#pragma unroll
        for (int i = 0; i < 16; i++) {
            int idx = t + i * 256;
            int o = idx >> 5, kq = idx & 31;
            *(float4*)(Ws + o * HL_STR + kq * 4) = *(const float4*)(W + (size_t)o * Hn + kq * 4);
        }
        __syncthreads();
        float acc0[4] = {0.f, 0.f, 0.f, 0.f};
        float acc1[4] = {0.f, 0.f, 0.f, 0.f};
#pragma unroll 4
        for (int k4 = 0; k4 < 32; k4++) {
            float4 h0 = *(const float4*)(hs + r0 * HL_STR + k4 * 4);
            float4 h1 = *(const float4*)(hs + r1 * HL_STR + k4 * 4);
#pragma unroll
            for (int c = 0; c < 4; c++) {
                float4 w = *(const float4*)(Ws + (lane + 32 * c) * HL_STR + k4 * 4);
                acc0[c] += h0.x * w.x + h0.y * w.y + h0.z * w.z + h0.w * w.w;
                acc1[c] += h1.x * w.x + h1.y * w.y + h1.z * w.z + h1.w * w.w;
            }
        }
        float* O = Op[a];
        const float* bb = bp[a];
#pragma unroll
        for (int c = 0; c < 4; c++) {
            int col = lane + 32 * c;
            float bv = bb[col];
            O[(size_t)(rbase + r0) * Hn + col] = acc0[c] + bv;
            O[(size_t)(rbase + r1) * Hn + col] = acc1[c] + bv;
        }
    }
}

// Pass 1: tf32 mma.sync GEMM + coalesced fused epilogue, 2 CTAs/SM,
// 2 independent 4-warp groups per CTA (named barriers), 32-row chunks.
// W stored PAIRED (float2 of k,k+4) so each B-fragment is one LDS.64.
// e_new spilled as fp16 (half2 pairs), stats kept fp32.
#define AS_STRIDE 132
#define WP_FLOATS 16896               /* 64*132 float2 */
#define BUF_FLOATS 4224               /* 32*132 */
#define GS_OFF    25344               /* 16896 + 2*4224 */
#define SMEM_FLOATS 25600             /* 102400 B -> 2 CTAs/SM */
// reduction scratch inside retired Wp area (floats): 8 warps x 132
#define RED_SQ    1056
#define RED_AGG   2112

__global__ __launch_bounds__(256, 2)
void k_pass1(const float* __restrict__ e,
             const int* __restrict__ graph,
             const float* __restrict__ Cw,
             const float* __restrict__ Cb) {
    extern __shared__ float sm[];
    uint32_t* WpU = (uint32_t*)sm;
    int* gs = (int*)(sm + GS_OFF);

    const int p = blockIdx.x, b = p >> 8;
    const int t = threadIdx.x;
    const int lane = t & 31, wid = t >> 5;
    const int g  = wid >> 2;              // group 0/1
    const int wq = wid & 3;               // warp-in-group = h block
    const int gid = lane >> 2, tig = lane & 3;
    const int barid = g + 1;

    float* As = sm + WP_FLOATS + g * BUF_FLOATS;   // group-private 32-row buffer
    const unsigned dbase = smem_u32(As);
    const float* ebase = e + (size_t)p * Vn * Hn;
    const int gt = t & 127;

    // issue first chunk for own group (chunk rows j0 = g*32)
    {
        int j0 = g * 32;
#pragma unroll
        for (int i = 0; i < 8; i++) {
            int fid = i * 128 + gt;
            int row = fid >> 5, kq = fid & 31;
            cp_async16(dbase + (row * AS_STRIDE + kq * 4) * 4,
                       ebase + (size_t)(j0 + row) * Hn + kq * 4);
        }
        asm volatile("cp.async.commit_group;\n");
    }

    // stage paired W (coalesced LDG over Cw[n][k])
    for (int i = t; i < Hn * Hn; i += 256) {
        int n = i >> 7, k = i & 127;
        WpU[(((k >> 3) * 4 + (k & 3)) * AS_STRIDE + n) * 2 + ((k >> 2) & 1)] = f2tf32(Cw[i]);
    }
    gs[t] = graph[p * Vn + t];

    const int h4 = lane * 4;
    float4 bias4;
    {
        float4 bb = *(const float4*)(g_Bh + (size_t)p * Hn + h4);
        float4 cb = *(const float4*)(Cb + h4);
        bias4 = make_float4(bb.x + cb.x, bb.y + cb.y, bb.z + cb.z, bb.w + cb.w);
    }
    float4 sum4 = make_float4(0.f, 0.f, 0.f, 0.f);
    float4 sq4  = make_float4(0.f, 0.f, 0.f, 0.f);
    float4 agg4 = make_float4(0.f, 0.f, 0.f, 0.f);

    __syncthreads();    // W + gs visible everywhere

    const uint32_t* AbufU = (const uint32_t*)As;
    const uint2* Wp2 = (const uint2*)sm;
    const float* AhB = g_Ah + (size_t)b * Vn * Hn;
    const float* VhB = g_Vh + (size_t)b * Vn * Hn;

    for (int c = 0; c < 4; c++) {
        const int j0 = (c * 2 + g) * 32;
        asm volatile("cp.async.wait_group 0;\n" ::: "memory");
        asm volatile("bar.sync %0, 128;" :: "r"(barid) : "memory");

        // ---- GEMM: warp tile 32(j) x 32(h) over the 32-row chunk ----
        float cf[2][4][4];
#pragma unroll
        for (int rg = 0; rg < 2; rg++)
#pragma unroll
            for (int nt = 0; nt < 4; nt++)
#pragma unroll
                for (int q = 0; q < 4; q++) cf[rg][nt][q] = 0.f;

#pragma unroll 2
        for (int ks = 0; ks < 16; ks++) {
            int k0 = ks * 8 + tig;
            uint32_t a[2][4];
#pragma unroll
            for (int rg = 0; rg < 2; rg++) {
                int r = rg * 16 + gid;
                a[rg][0] = AbufU[r * AS_STRIDE + k0];
                a[rg][1] = AbufU[(r + 8) * AS_STRIDE + k0];
                a[rg][2] = AbufU[r * AS_STRIDE + k0 + 4];
                a[rg][3] = AbufU[(r + 8) * AS_STRIDE + k0 + 4];
            }
            uint2 bfr[4];
#pragma unroll
            for (int nt = 0; nt < 4; nt++)
                bfr[nt] = Wp2[(ks * 4 + tig) * AS_STRIDE + wq * 32 + nt * 8 + gid];
#pragma unroll
            for (int rg = 0; rg < 2; rg++)
#pragma unroll
                for (int nt = 0; nt < 4; nt++) {
                    asm volatile(
                        "mma.sync.aligned.m16n8k8.row.col.f32.tf32.tf32.f32 "
                        "{%0,%1,%2,%3},{%4,%5,%6,%7},{%8,%9},{%0,%1,%2,%3};"
                        : "+f"(cf[rg][nt][0]), "+f"(cf[rg][nt][1]),
                          "+f"(cf[rg][nt][2]), "+f"(cf[rg][nt][3])
                        : "r"(a[rg][0]), "r"(a[rg][1]), "r"(a[rg][2]), "r"(a[rg][3]),
                          "r"(bfr[nt].x), "r"(bfr[nt].y));
                }
        }

        asm volatile("bar.sync %0, 128;" :: "r"(barid) : "memory");
        // ---- transpose fragments into the dead chunk buffer ----
#pragma unroll
        for (int rg = 0; rg < 2; rg++)
#pragma unroll
            for (int half = 0; half < 2; half++) {
                int jl = rg * 16 + half * 8 + gid;
#pragma unroll
                for (int nt = 0; nt < 4; nt++) {
                    int h = wq * 32 + nt * 8 + tig * 2;
                    *(float2*)(As + jl * AS_STRIDE + h) =
                        make_float2(cf[rg][nt][half * 2], cf[rg][nt][half * 2 + 1]);
                }
            }
        asm volatile("bar.sync %0, 128;" :: "r"(barid) : "memory");

        // ---- coalesced epilogue: warp owns rows [wq*8, wq*8+8) of chunk ----
#pragma unroll
        for (int r = 0; r < 8; r++) {
            int jl = wq * 8 + r;
            int j  = j0 + jl;
            float4 cv = *(const float4*)(As + jl * AS_STRIDE + h4);
            float4 ah = *(const float4*)(AhB + (size_t)j * Hn + h4);
            float4 en;
            en.x = cv.x + ah.x + bias4.x;
            en.y = cv.y + ah.y + bias4.y;
            en.z = cv.z + ah.z + bias4.z;
            en.w = cv.w + ah.w + bias4.w;
            // fp16 spill (streaming store, 8B/thread coalesced)
            {
                __half2 ha = __floats2half2_rn(en.x, en.y);
                __half2 hb = __floats2half2_rn(en.z, en.w);
                uint2 pk;
                pk.x = *(uint32_t*)&ha;
                pk.y = *(uint32_t*)&hb;
                __stcs((uint2*)(g_enew + ((size_t)p * Vn + j) * Hn) + lane, pk);
            }
            sum4.x += en.x; sum4.y += en.y; sum4.z += en.z; sum4.w += en.w;
            sq4.x += en.x * en.x; sq4.y += en.y * en.y;
            sq4.z += en.z * en.z; sq4.w += en.w * en.w;
            if (!gs[j]) {
                float4 vh = *(const float4*)(VhB + (size_t)j * Hn + h4);
                agg4.x += fast_sigmoid(en.x) * vh.x;
                agg4.y += fast_sigmoid(en.y) * vh.y;
                agg4.z += fast_sigmoid(en.z) * vh.z;
                agg4.w += fast_sigmoid(en.w) * vh.w;
            }
        }
        asm volatile("bar.sync %0, 128;" :: "r"(barid) : "memory");

        if (c < 3) {
            int jn = ((c + 1) * 2 + g) * 32;
#pragma unroll
            for (int i = 0; i < 8; i++) {
                int fid = i * 128 + gt;
                int row = fid >> 5, kq = fid & 31;
                cp_async16(dbase + (row * AS_STRIDE + kq * 4) * 4,
                           ebase + (size_t)(jn + row) * Hn + kq * 4);
            }
            asm volatile("cp.async.commit_group;\n");
        }
    }

    // ---- block reduction via retired Wp area ----
    float* redS = sm;
    __syncthreads();
    *(float4*)(redS + wid * AS_STRIDE + h4)           = sum4;
    *(float4*)(redS + RED_SQ + wid * AS_STRIDE + h4)  = sq4;
    *(float4*)(redS + RED_AGG + wid * AS_STRIDE + h4) = agg4;
    __syncthreads();
    if (t < Hn) {
        float s = 0.f, q = 0.f, gg = 0.f;
#pragma unroll
        for (int w = 0; w < 8; w++) {
            s  += redS[w * AS_STRIDE + t];
            q  += redS[RED_SQ + w * AS_STRIDE + t];
            gg += redS[RED_AGG + w * AS_STRIDE + t];
        }
        atomicAdd(&g_esum[t], s);
        atomicAdd(&g_esq[t],  q);
        g_hnew[(size_t)p * Hn + t] = g_Uh[(size_t)p * Hn + t] + gg;
    }
}

// pass 2 over e: normalize + relu + residual (blocks < 65536), h-side
// batchnorm as tail blocks. BN scale/shift derived in-block from g_esum/g_esq.
__global__ void k_epass2(const float* __restrict__ ein,
                         float* __restrict__ eout,
                         const float* __restrict__ game,
                         const float* __restrict__ bete,
                         const float* __restrict__ hin,
                         const float* __restrict__ gamh,
                         const float* __restrict__ beth,
                         float* __restrict__ hout) {
    if (blockIdx.x < 65536) {
        __shared__ float scS[128], shS[128];
        int t = threadIdx.x;
        if (t < 128) {
            float mean = g_esum[t] * (1.0f / NE);
            float var  = g_esq[t] * (1.0f / NE) - mean * mean;
            float sc = game[t] * rsqrtf(var + 1e-5f);
            scS[t] = sc;
            shS[t] = bete[t] - mean * sc;
        }
        __syncthreads();
        size_t idx = (size_t)blockIdx.x * blockDim.x + t;   // 4-channel unit idx
        int h0 = (int)((idx * 4) & 127);
        uint2 pk = __ldcs((const uint2*)g_enew + idx);
        __half2 ha = *(__half2*)&pk.x;
        __half2 hb = *(__half2*)&pk.y;
        float2 f01 = __half22float2(ha);
        float2 f23 = __half22float2(hb);
        float4 a = __ldcs((const float4*)ein + idx);
        float4 o;
        o.x = a.x + fmaxf(f01.x * scS[h0]     + shS[h0],     0.f);
        o.y = a.y + fmaxf(f01.y * scS[h0 + 1] + shS[h0 + 1], 0.f);
        o.z = a.z + fmaxf(f23.x * scS[h0 + 2] + shS[h0 + 2], 0.f);
        o.w = a.w + fmaxf(f23.y * scS[h0 + 3] + shS[h0 + 3], 0.f);
        ((float4*)eout)[idx] = o;
    } else {
        int h = blockIdx.x - 65536, t = threadIdx.x;
        float v[8];
        float s = 0.f, q = 0.f;
#pragma unroll
        for (int r = 0; r < 8; r++) {
            float x = g_hnew[(size_t)(t * 8 + r) * Hn + h];
            v[r] = x; s += x; q += x * x;
        }
        __shared__ float rs[256], rq[256];
        rs[t] = s; rq[t] = q; __syncthreads();
        for (int o = 128; o > 0; o >>= 1) {
            if (t < o) { rs[t] += rs[t + o]; rq[t] += rq[t + o]; }
            __syncthreads();
        }
        __shared__ float sc, sh;
        if (t == 0) {
            float mean = rs[0] * (1.0f / NR);
            float var  = rq[0] * (1.0f / NR) - mean * mean;
            float scale = gamh[h] * rsqrtf(var + 1e-5f);
            sc = scale; sh = beth[h] - mean * scale;
        }
        __syncthreads();
#pragma unroll
        for (int r = 0; r < 8; r++) {
            int row = t * 8 + r;
            float y = fmaxf(v[r] * sc + sh, 0.f);
            hout[(size_t)row * Hn + h] = hin[(size_t)row * Hn + h] + y;
        }
    }
}

// ---------------- launch ----------------
extern "C" void kernel_launch(void* const* d_in, const int* in_sizes, int n_in,
                              void* d_out, int out_size) {
    const float* h   = (const float*)d_in[0];
    const float* e   = (const float*)d_in[1];
    const int*   gra = (const int*)  d_in[2];
    const float* Uw  = (const float*)d_in[3],  *Ub = (const float*)d_in[4];
    const float* Vw  = (const float*)d_in[5],  *Vb = (const float*)d_in[6];
    const float* Aw  = (const float*)d_in[7],  *Ab = (const float*)d_in[8];
    const float* Bw  = (const float*)d_in[9],  *Bb = (const float*)d_in[10];
    const float* Cw  = (const float*)d_in[11], *Cb = (const float*)d_in[12];
    const float* gh  = (const float*)d_in[13], *bh = (const float*)d_in[14];
    const float* ge  = (const float*)d_in[15], *be = (const float*)d_in[16];

    float* out  = (float*)d_out;
    float* hout = out;                        // [2048,128]
    float* eout = out + (size_t)NR * Hn;      // [8,256,256,128]

    const int smemE = SMEM_FLOATS * 4;        // 102400 B -> 2 CTAs/SM
    cudaFuncSetAttribute(k_pass1, cudaFuncAttributeMaxDynamicSharedMemorySize, smemE);

    k_hlin4 <<<256, 256>>>(h, Uw, Ub, Vw, Vb, Aw, Ab, Bw, Bb);
    k_pass1 <<<NR, 256, smemE>>>(e, gra, Cw, Cb);
    k_epass2<<<65664, 256>>>(e, eout, ge, be, h, gh, bh, hout);
}

// round 14
// speedup vs baseline: 1.1590x; 1.0104x over previous
#include <cuda_runtime.h>
#include <cuda_fp16.h>
#include <math.h>
#include <stdint.h>

#define Bdim 8
#define Vn   256
#define Hn   128
#define NR   2048      /* B*V   */
#define NE   524288    /* B*V*V */
#define NPERS 296      /* persistent CTAs: 2 per SM */

// ---------------- device scratch (no allocation allowed) ----------------
__device__ float g_Uh[NR * Hn];
__device__ float g_Vh[NR * Hn];
__device__ float g_Ah[NR * Hn];
__device__ float g_Bh[NR * Hn];
__device__ float g_hnew[NR * Hn];
__device__ float g_esum[Hn];
__device__ float g_esq[Hn];
__device__ __half g_enew[(size_t)NE * Hn];   // 134 MB fp16 spill of e_new

// ---------------- helpers ----------------
__device__ __forceinline__ unsigned smem_u32(const void* p) {
    unsigned a;
    asm("{ .reg .u64 t; cvta.to.shared.u64 t, %1; cvt.u32.u64 %0, t; }"
        : "=r"(a) : "l"(p));
    return a;
}
__device__ __forceinline__ void cp_async16(unsigned dst, const void* src) {
    asm volatile("cp.async.cg.shared.global [%0], [%1], 16;\n" :: "r"(dst), "l"(src));
}
__device__ __forceinline__ uint32_t f2tf32(float f) {
    uint32_t u;
    asm("cvt.rna.tf32.f32 %0, %1;" : "=r"(u) : "f"(f));
    return u;
}
__device__ __forceinline__ float fast_sigmoid(float x) {
    float t;
    asm("tanh.approx.f32 %0, %1;" : "=f"(t) : "f"(0.5f * x));
    return 0.5f * t + 0.5f;
}

// ---------------- kernels ----------------

// all four h-linears in ONE launch: blocks 0..127 -> U/V, 128..255 -> A/B.
// block 0 also zeroes the BN accumulators.
#define HL_STR 132
__global__ __launch_bounds__(256)
void k_hlin4(const float* __restrict__ h,
             const float* __restrict__ Uw, const float* __restrict__ Ub,
             const float* __restrict__ Vw, const float* __restrict__ Vb,
             const float* __restrict__ Aw, const float* __restrict__ Ab,
             const float* __restrict__ Bw, const float* __restrict__ Bb) {
    __shared__ float hs[16 * HL_STR];
    __shared__ float Ws[128 * HL_STR];
    const int t = threadIdx.x;
    const int lane = t & 31, wq = t >> 5;
    const int which = blockIdx.x >> 7;
    const int rbase = (blockIdx.x & 127) * 16;
    if (blockIdx.x == 0 && t < Hn) { g_esum[t] = 0.f; g_esq[t] = 0.f; }
    {
        int idx0 = t, idx1 = t + 256;
        int r0 = idx0 >> 5, kq0 = idx0 & 31;
        int r1 = idx1 >> 5, kq1 = idx1 & 31;
        *(float4*)(hs + r0 * HL_STR + kq0 * 4) = *(const float4*)(h + (size_t)(rbase + r0) * Hn + kq0 * 4);
        *(float4*)(hs + r1 * HL_STR + kq1 * 4) = *(const float4*)(h + (size_t)(rbase + r1) * Hn + kq1 * 4);
    }
    const float* Wp[2]; const float* bp[2]; float* Op[2];
    if (which) { Wp[0] = Aw; Wp[1] = Bw; bp[0] = Ab; bp[1] = Bb; Op[0] = g_Ah; Op[1] = g_Bh; }
    else       { Wp[0] = Uw; Wp[1] = Vw; bp[0] = Ub; bp[1] = Vb; Op[0] = g_Uh; Op[1] = g_Vh; }
    const int r0 = wq * 2, r1 = wq * 2 + 1;
    for (int a = 0; a < 2; a++) {
        __syncthreads();
        const float* W = Wp[a];
#pragma unroll
        for (int i = 0; i < 16; i++) {
            int idx = t + i * 256;
            int o = idx >> 5, kq = idx & 31;
            *(float4*)(Ws + o * HL_STR + kq * 4) = *(const float4*)(W + (size_t)o * Hn + kq * 4);
        }
        __syncthreads();
        float acc0[4] = {0.f, 0.f, 0.f, 0.f};
        float acc1[4] = {0.f, 0.f, 0.f, 0.f};
#pragma unroll 4
        for (int k4 = 0; k4 < 32; k4++) {
            float4 h0 = *(const float4*)(hs + r0 * HL_STR + k4 * 4);
            float4 h1 = *(const float4*)(hs + r1 * HL_STR + k4 * 4);
#pragma unroll
            for (int c = 0; c < 4; c++) {
                float4 w = *(const float4*)(Ws + (lane + 32 * c) * HL_STR + k4 * 4);
                acc0[c] += h0.x * w.x + h0.y * w.y + h0.z * w.z + h0.w * w.w;
                acc1[c] += h1.x * w.x + h1.y * w.y + h1.z * w.z + h1.w * w.w;
            }
        }
        float* O = Op[a];
        const float* bb = bp[a];
#pragma unroll
        for (int c = 0; c < 4; c++) {
            int col = lane + 32 * c;
            float bv = bb[col];
            O[(size_t)(rbase + r0) * Hn + col] = acc0[c] + bv;
            O[(size_t)(rbase + r1) * Hn + col] = acc1[c] + bv;
        }
    }
}

// Pass 1: PERSISTENT tf32 mma.sync GEMM + coalesced fused epilogue.
// 296 CTAs (2/SM), each stages the paired W tile ONCE and loops over
// p-tiles with stride 296. 2 independent 4-warp groups per CTA (named
// barriers), 32-row chunks; cross-tile chunk prefetch keeps cp.async busy.
// e_new spilled fp16; BN sum/sq accumulate in registers across all tiles.
#define AS_STRIDE 132
#define WP_FLOATS 16896               /* 64*132 float2 */
#define BUF_FLOATS 4224               /* 32*132 */
#define BUF_OFF   16896
#define GS_OFF    25344               /* 2 x 256 ints (per-group graph row) */
#define AGG_OFF   25856
#define SUM_OFF   25984
#define SQ_OFF    26112
#define SMEM_FLOATS 26240             /* 104960 B -> 2 CTAs/SM */

__global__ __launch_bounds__(256, 2)
void k_pass1(const float* __restrict__ e,
             const int* __restrict__ graph,
             const float* __restrict__ Cw,
             const float* __restrict__ Cb) {
    extern __shared__ float sm[];
    uint32_t* WpU = (uint32_t*)sm;

    const int t = threadIdx.x;
    const int lane = t & 31, wid = t >> 5;
    const int g  = wid >> 2;              // group 0/1
    const int wq = wid & 3;               // warp-in-group = h block
    const int gid = lane >> 2, tig = lane & 3;
    const int barid = g + 1;
    const int gt = t & 127;

    int*   gsG  = (int*)(sm + GS_OFF) + g * 256;
    float* aggS = sm + AGG_OFF;
    float* sumS = sm + SUM_OFF;
    float* sqS  = sm + SQ_OFF;

    float* As = sm + BUF_OFF + g * BUF_FLOATS;   // group-private 32-row buffer
    const unsigned dbase = smem_u32(As);

    if (t < 128) { aggS[t] = 0.f; sumS[t] = 0.f; sqS[t] = 0.f; }

    // prefetch first tile's chunk 0 (overlaps W staging)
    {
        const float* eb0 = e + (size_t)blockIdx.x * Vn * Hn;
#pragma unroll
        for (int i = 0; i < 8; i++) {
            int fid = i * 128 + gt;
            int row = fid >> 5, kq = fid & 31;
            cp_async16(dbase + (row * AS_STRIDE + kq * 4) * 4,
                       eb0 + (size_t)(g * 32 + row) * Hn + kq * 4);
        }
        asm volatile("cp.async.commit_group;\n");
    }

    // stage paired W ONCE (coalesced LDG over Cw[n][k])
    for (int i = t; i < Hn * Hn; i += 256) {
        int n = i >> 7, k = i & 127;
        WpU[(((k >> 3) * 4 + (k & 3)) * AS_STRIDE + n) * 2 + ((k >> 2) & 1)] = f2tf32(Cw[i]);
    }
    __syncthreads();    // W + zeroed reductions visible

    const int h4 = lane * 4;
    float4 sum4 = make_float4(0.f, 0.f, 0.f, 0.f);
    float4 sq4  = make_float4(0.f, 0.f, 0.f, 0.f);

    const uint32_t* AbufU = (const uint32_t*)As;
    const uint2* Wp2 = (const uint2*)sm;

    for (int p = blockIdx.x; p < NR; p += NPERS) {
        const int b = p >> 8;
        const float* ebase = e + (size_t)p * Vn * Hn;
        const float* AhB = g_Ah + (size_t)b * Vn * Hn;
        const float* VhB = g_Vh + (size_t)b * Vn * Hn;

        // per-tile group-private graph row (safe: prior tile's reads ended
        // before the tile-boundary __syncthreads)
        gsG[gt]       = graph[p * Vn + gt];
        gsG[gt + 128] = graph[p * Vn + gt + 128];

        float4 bias4;
        {
            float4 bb = *(const float4*)(g_Bh + (size_t)p * Hn + h4);
            float4 cb = *(const float4*)(Cb + h4);
            bias4 = make_float4(bb.x + cb.x, bb.y + cb.y, bb.z + cb.z, bb.w + cb.w);
        }
        float4 agg4 = make_float4(0.f, 0.f, 0.f, 0.f);

        for (int c = 0; c < 4; c++) {
            const int j0 = (c * 2 + g) * 32;
            asm volatile("cp.async.wait_group 0;\n" ::: "memory");
            asm volatile("bar.sync %0, 128;" :: "r"(barid) : "memory");

            // ---- GEMM: warp tile 32(j) x 32(h) over the 32-row chunk ----
            float cf[2][4][4];
#pragma unroll
            for (int rg = 0; rg < 2; rg++)
#pragma unroll
                for (int nt = 0; nt < 4; nt++)
#pragma unroll
                    for (int q = 0; q < 4; q++) cf[rg][nt][q] = 0.f;

#pragma unroll 2
            for (int ks = 0; ks < 16; ks++) {
                int k0 = ks * 8 + tig;
                uint32_t a[2][4];
#pragma unroll
                for (int rg = 0; rg < 2; rg++) {
                    int r = rg * 16 + gid;
                    a[rg][0] = AbufU[r * AS_STRIDE + k0];
                    a[rg][1] = AbufU[(r + 8) * AS_STRIDE + k0];
                    a[rg][2] = AbufU[r * AS_STRIDE + k0 + 4];
                    a[rg][3] = AbufU[(r + 8) * AS_STRIDE + k0 + 4];
                }
                uint2 bfr[4];
#pragma unroll
                for (int nt = 0; nt < 4; nt++)
                    bfr[nt] = Wp2[(ks * 4 + tig) * AS_STRIDE + wq * 32 + nt * 8 + gid];
#pragma unroll
                for (int rg = 0; rg < 2; rg++)
#pragma unroll
                    for (int nt = 0; nt < 4; nt++) {
                        asm volatile(
                            "mma.sync.aligned.m16n8k8.row.col.f32.tf32.tf32.f32 "
                            "{%0,%1,%2,%3},{%4,%5,%6,%7},{%8,%9},{%0,%1,%2,%3};"
                            : "+f"(cf[rg][nt][0]), "+f"(cf[rg][nt][1]),
                              "+f"(cf[rg][nt][2]), "+f"(cf[rg][nt][3])
                            : "r"(a[rg][0]), "r"(a[rg][1]), "r"(a[rg][2]), "r"(a[rg][3]),
                              "r"(bfr[nt].x), "r"(bfr[nt].y));
                    }
            }

            asm volatile("bar.sync %0, 128;" :: "r"(barid) : "memory");
            // ---- transpose fragments into the dead chunk buffer ----
#pragma unroll
            for (int rg = 0; rg < 2; rg++)
#pragma unroll
                for (int half = 0; half < 2; half++) {
                    int jl = rg * 16 + half * 8 + gid;
#pragma unroll
                    for (int nt = 0; nt < 4; nt++) {
                        int h = wq * 32 + nt * 8 + tig * 2;
                        *(float2*)(As + jl * AS_STRIDE + h) =
                            make_float2(cf[rg][nt][half * 2], cf[rg][nt][half * 2 + 1]);
                    }
                }
            asm volatile("bar.sync %0, 128;" :: "r"(barid) : "memory");

            // ---- coalesced epilogue: warp owns rows [wq*8, wq*8+8) ----
#pragma unroll
            for (int r = 0; r < 8; r++) {
                int jl = wq * 8 + r;
                int j  = j0 + jl;
                float4 cv = *(const float4*)(As + jl * AS_STRIDE + h4);
                float4 ah = *(const float4*)(AhB + (size_t)j * Hn + h4);
                float4 en;
                en.x = cv.x + ah.x + bias4.x;
                en.y = cv.y + ah.y + bias4.y;
                en.z = cv.z + ah.z + bias4.z;
                en.w = cv.w + ah.w + bias4.w;
                {
                    __half2 ha = __floats2half2_rn(en.x, en.y);
                    __half2 hb = __floats2half2_rn(en.z, en.w);
                    uint2 pk;
                    pk.x = *(uint32_t*)&ha;
                    pk.y = *(uint32_t*)&hb;
                    __stcs((uint2*)(g_enew + ((size_t)p * Vn + j) * Hn) + lane, pk);
                }
                sum4.x += en.x; sum4.y += en.y; sum4.z += en.z; sum4.w += en.w;
                sq4.x += en.x * en.x; sq4.y += en.y * en.y;
                sq4.z += en.z * en.z; sq4.w += en.w * en.w;
                if (!gsG[j]) {
                    float4 vh = *(const float4*)(VhB + (size_t)j * Hn + h4);
                    agg4.x += fast_sigmoid(en.x) * vh.x;
                    agg4.y += fast_sigmoid(en.y) * vh.y;
                    agg4.z += fast_sigmoid(en.z) * vh.z;
                    agg4.w += fast_sigmoid(en.w) * vh.w;
                }
            }
            asm volatile("bar.sync %0, 128;" :: "r"(barid) : "memory");

            // ---- prefetch: next chunk of this tile, or next tile's chunk 0 ----
            if (c < 3) {
                int jn = ((c + 1) * 2 + g) * 32;
#pragma unroll
                for (int i = 0; i < 8; i++) {
                    int fid = i * 128 + gt;
                    int row = fid >> 5, kq = fid & 31;
                    cp_async16(dbase + (row * AS_STRIDE + kq * 4) * 4,
                               ebase + (size_t)(jn + row) * Hn + kq * 4);
                }
                asm volatile("cp.async.commit_group;\n");
            } else if (p + NPERS < NR) {
                const float* ebn = e + (size_t)(p + NPERS) * Vn * Hn;
#pragma unroll
                for (int i = 0; i < 8; i++) {
                    int fid = i * 128 + gt;
                    int row = fid >> 5, kq = fid & 31;
                    cp_async16(dbase + (row * AS_STRIDE + kq * 4) * 4,
                               ebn + (size_t)(g * 32 + row) * Hn + kq * 4);
                }
                asm volatile("cp.async.commit_group;\n");
            }
        }

        // ---- per-tile gated-aggregation reduction (block-wide) ----
        __syncthreads();
        atomicAdd(&aggS[h4],     agg4.x);
        atomicAdd(&aggS[h4 + 1], agg4.y);
        atomicAdd(&aggS[h4 + 2], agg4.z);
        atomicAdd(&aggS[h4 + 3], agg4.w);
        __syncthreads();
        if (t < Hn) {
            g_hnew[(size_t)p * Hn + t] = g_Uh[(size_t)p * Hn + t] + aggS[t];
            aggS[t] = 0.f;   // next tile's atomics are after its own __syncthreads
        }
    }

    // ---- final BN stats reduction (once per CTA) ----
    __syncthreads();
    atomicAdd(&sumS[h4],     sum4.x);
    atomicAdd(&sumS[h4 + 1], sum4.y);
    atomicAdd(&sumS[h4 + 2], sum4.z);
    atomicAdd(&sumS[h4 + 3], sum4.w);
    atomicAdd(&sqS[h4],      sq4.x);
    atomicAdd(&sqS[h4 + 1],  sq4.y);
    atomicAdd(&sqS[h4 + 2],  sq4.z);
    atomicAdd(&sqS[h4 + 3],  sq4.w);
    __syncthreads();
    if (t < Hn) {
        atomicAdd(&g_esum[t], sumS[t]);
        atomicAdd(&g_esq[t],  sqS[t]);
    }
}

// pass 2 over e: normalize + relu + residual (blocks < 65536), h-side
// batchnorm as tail blocks. BN scale/shift derived in-block from g_esum/g_esq.
__global__ void k_epass2(const float* __restrict__ ein,
                         float* __restrict__ eout,
                         const float* __restrict__ game,
                         const float* __restrict__ bete,
                         const float* __restrict__ hin,
                         const float* __restrict__ gamh,
                         const float* __restrict__ beth,
                         float* __restrict__ hout) {
    if (blockIdx.x < 65536) {
        __shared__ float scS[128], shS[128];
        int t = threadIdx.x;
        if (t < 128) {
            float mean = g_esum[t] * (1.0f / NE);
            float var  = g_esq[t] * (1.0f / NE) - mean * mean;
            float sc = game[t] * rsqrtf(var + 1e-5f);
            scS[t] = sc;
            shS[t] = bete[t] - mean * sc;
        }
        __syncthreads();
        size_t idx = (size_t)blockIdx.x * blockDim.x + t;   // 4-channel unit idx
        int h0 = (int)((idx * 4) & 127);
        uint2 pk = __ldcs((const uint2*)g_enew + idx);
        __half2 ha = *(__half2*)&pk.x;
        __half2 hb = *(__half2*)&pk.y;
        float2 f01 = __half22float2(ha);
        float2 f23 = __half22float2(hb);
        float4 a = __ldcs((const float4*)ein + idx);
        float4 o;
        o.x = a.x + fmaxf(f01.x * scS[h0]     + shS[h0],     0.f);
        o.y = a.y + fmaxf(f01.y * scS[h0 + 1] + shS[h0 + 1], 0.f);
        o.z = a.z + fmaxf(f23.x * scS[h0 + 2] + shS[h0 + 2], 0.f);
        o.w = a.w + fmaxf(f23.y * scS[h0 + 3] + shS[h0 + 3], 0.f);
        ((float4*)eout)[idx] = o;
    } else {
        int h = blockIdx.x - 65536, t = threadIdx.x;
        float v[8];
        float s = 0.f, q = 0.f;
#pragma unroll
        for (int r = 0; r < 8; r++) {
            float x = g_hnew[(size_t)(t * 8 + r) * Hn + h];
            v[r] = x; s += x; q += x * x;
        }
        __shared__ float rs[256], rq[256];
        rs[t] = s; rq[t] = q; __syncthreads();
        for (int o = 128; o > 0; o >>= 1) {
            if (t < o) { rs[t] += rs[t + o]; rq[t] += rq[t + o]; }
            __syncthreads();
        }
        __shared__ float sc, sh;
        if (t == 0) {
            float mean = rs[0] * (1.0f / NR);
            float var  = rq[0] * (1.0f / NR) - mean * mean;
            float scale = gamh[h] * rsqrtf(var + 1e-5f);
            sc = scale; sh = beth[h] - mean * scale;
        }
        __syncthreads();
#pragma unroll
        for (int r = 0; r < 8; r++) {
            int row = t * 8 + r;
            float y = fmaxf(v[r] * sc + sh, 0.f);
            hout[(size_t)row * Hn + h] = hin[(size_t)row * Hn + h] + y;
        }
    }
}

// ---------------- launch ----------------
extern "C" void kernel_launch(void* const* d_in, const int* in_sizes, int n_in,
                              void* d_out, int out_size) {
    const float* h   = (const float*)d_in[0];
    const float* e   = (const float*)d_in[1];
    const int*   gra = (const int*)  d_in[2];
    const float* Uw  = (const float*)d_in[3],  *Ub = (const float*)d_in[4];
    const float* Vw  = (const float*)d_in[5],  *Vb = (const float*)d_in[6];
    const float* Aw  = (const float*)d_in[7],  *Ab = (const float*)d_in[8];
    const float* Bw  = (const float*)d_in[9],  *Bb = (const float*)d_in[10];
    const float* Cw  = (const float*)d_in[11], *Cb = (const float*)d_in[12];
    const float* gh  = (const float*)d_in[13], *bh = (const float*)d_in[14];
    const float* ge  = (const float*)d_in[15], *be = (const float*)d_in[16];

    float* out  = (float*)d_out;
    float* hout = out;                        // [2048,128]
    float* eout = out + (size_t)NR * Hn;      // [8,256,256,128]

    const int smemE = SMEM_FLOATS * 4;        // 104960 B -> 2 CTAs/SM
    cudaFuncSetAttribute(k_pass1, cudaFuncAttributeMaxDynamicSharedMemorySize, smemE);

    k_hlin4 <<<256, 256>>>(h, Uw, Ub, Vw, Vb, Aw, Ab, Bw, Bb);
    k_pass1 <<<NPERS, 256, smemE>>>(e, gra, Cw, Cb);
    k_epass2<<<65664, 256>>>(e, eout, ge, be, h, gh, bh, hout);
}

// round 15
// speedup vs baseline: 1.2161x; 1.0493x over previous
#include <cuda_runtime.h>
#include <cuda_fp16.h>
#include <math.h>
#include <stdint.h>

#define Bdim 8
#define Vn   256
#define Hn   128
#define NR   2048      /* B*V   */
#define NE   524288    /* B*V*V */
#define NPERS 296      /* persistent CTAs: 2 per SM */

// ---------------- device scratch (no allocation allowed) ----------------
__device__ float g_Uh[NR * Hn];
__device__ float g_Vh[NR * Hn];
__device__ float g_Ah[NR * Hn];
__device__ float g_Bh[NR * Hn];
__device__ float g_hnew[NR * Hn];
__device__ float g_esum[Hn];
__device__ float g_esq[Hn];
__device__ __half g_enew[(size_t)NE * Hn];   // 134 MB fp16 spill of e_new

// ---------------- helpers ----------------
__device__ __forceinline__ unsigned smem_u32(const void* p) {
    unsigned a;
    asm("{ .reg .u64 t; cvta.to.shared.u64 t, %1; cvt.u32.u64 %0, t; }"
        : "=r"(a) : "l"(p));
    return a;
}
__device__ __forceinline__ void cp_async16(unsigned dst, const void* src) {
    asm volatile("cp.async.cg.shared.global [%0], [%1], 16;\n" :: "r"(dst), "l"(src));
}
__device__ __forceinline__ uint32_t f2tf32(float f) {
    uint32_t u;
    asm("cvt.rna.tf32.f32 %0, %1;" : "=r"(u) : "f"(f));
    return u;
}
__device__ __forceinline__ float fast_sigmoid(float x) {
    float t;
    asm("tanh.approx.f32 %0, %1;" : "=f"(t) : "f"(0.5f * x));
    return 0.5f * t + 0.5f;
}

// ---------------- kernels ----------------

// h-linears: 256 blocks, each handles ONE weight array (which = blk>>6) for
// 32 rows. 4 rows x 4 cols per thread. Block 0 zeroes BN accumulators.
#define HL_STR 132
__global__ __launch_bounds__(256)
void k_hlin4(const float* __restrict__ h,
             const float* __restrict__ Uw, const float* __restrict__ Ub,
             const float* __restrict__ Vw, const float* __restrict__ Vb,
             const float* __restrict__ Aw, const float* __restrict__ Ab,
             const float* __restrict__ Bw, const float* __restrict__ Bb) {
    __shared__ float hs[32 * HL_STR];
    __shared__ float Ws[128 * HL_STR];
    const int t = threadIdx.x;
    const int lane = t & 31, wq = t >> 5;
    const int which = blockIdx.x >> 6;
    const int rbase = (blockIdx.x & 63) * 32;
    if (blockIdx.x == 0 && t < Hn) { g_esum[t] = 0.f; g_esq[t] = 0.f; }

    // stage h tile (32 rows x 128): 1024 float4, 4 per thread
#pragma unroll
    for (int i = 0; i < 4; i++) {
        int idx = i * 256 + t;
        int r = idx >> 5, kq = idx & 31;
        *(float4*)(hs + r * HL_STR + kq * 4) =
            *(const float4*)(h + (size_t)(rbase + r) * Hn + kq * 4);
    }

    const float* W; const float* bb; float* O;
    if      (which == 0) { W = Uw; bb = Ub; O = g_Uh; }
    else if (which == 1) { W = Vw; bb = Vb; O = g_Vh; }
    else if (which == 2) { W = Aw; bb = Ab; O = g_Ah; }
    else                 { W = Bw; bb = Bb; O = g_Bh; }

    // stage W (128 x 128): 4096 float4, 16 per thread
#pragma unroll
    for (int i = 0; i < 16; i++) {
        int idx = t + i * 256;
        int o = idx >> 5, kq = idx & 31;
        *(float4*)(Ws + o * HL_STR + kq * 4) = *(const float4*)(W + (size_t)o * Hn + kq * 4);
    }
    __syncthreads();

    float acc[4][4];
#pragma unroll
    for (int q = 0; q < 4; q++)
#pragma unroll
        for (int c = 0; c < 4; c++) acc[q][c] = 0.f;

#pragma unroll 4
    for (int k4 = 0; k4 < 32; k4++) {
        float4 hv[4];
#pragma unroll
        for (int q = 0; q < 4; q++)
            hv[q] = *(const float4*)(hs + (wq * 4 + q) * HL_STR + k4 * 4);
#pragma unroll
        for (int c = 0; c < 4; c++) {
            float4 w = *(const float4*)(Ws + (lane + 32 * c) * HL_STR + k4 * 4);
#pragma unroll
            for (int q = 0; q < 4; q++)
                acc[q][c] += hv[q].x * w.x + hv[q].y * w.y + hv[q].z * w.z + hv[q].w * w.w;
        }
    }
#pragma unroll
    for (int c = 0; c < 4; c++) {
        int col = lane + 32 * c;
        float bv = bb[col];
#pragma unroll
        for (int q = 0; q < 4; q++)
            O[(size_t)(rbase + wq * 4 + q) * Hn + col] = acc[q][c] + bv;
    }
}

// Pass 1: PERSISTENT tf32 mma.sync GEMM + coalesced fused epilogue.
// 296 CTAs (2/SM), each stages the paired W tile ONCE and loops over
// p-tiles with stride 296. 2 independent 4-warp groups per CTA (named
// barriers), 32-row chunks; cross-tile chunk prefetch keeps cp.async busy.
// e_new spilled fp16; BN sum/sq accumulate in registers across all tiles.
#define AS_STRIDE 132
#define WP_FLOATS 16896               /* 64*132 float2 */
#define BUF_FLOATS 4224               /* 32*132 */
#define BUF_OFF   16896
#define GS_OFF    25344               /* 2 x 256 ints (per-group graph row) */
#define AGG_OFF   25856
#define SUM_OFF   25984
#define SQ_OFF    26112
#define SMEM_FLOATS 26240             /* 104960 B -> 2 CTAs/SM */

__global__ __launch_bounds__(256, 2)
void k_pass1(const float* __restrict__ e,
             const int* __restrict__ graph,
             const float* __restrict__ Cw,
             const float* __restrict__ Cb) {
    extern __shared__ float sm[];
    uint32_t* WpU = (uint32_t*)sm;

    const int t = threadIdx.x;
    const int lane = t & 31, wid = t >> 5;
    const int g  = wid >> 2;              // group 0/1
    const int wq = wid & 3;               // warp-in-group = h block
    const int gid = lane >> 2, tig = lane & 3;
    const int barid = g + 1;
    const int gt = t & 127;

    int*   gsG  = (int*)(sm + GS_OFF) + g * 256;
    float* aggS = sm + AGG_OFF;
    float* sumS = sm + SUM_OFF;
    float* sqS  = sm + SQ_OFF;

    float* As = sm + BUF_OFF + g * BUF_FLOATS;   // group-private 32-row buffer
    const unsigned dbase = smem_u32(As);

    if (t < 128) { aggS[t] = 0.f; sumS[t] = 0.f; sqS[t] = 0.f; }

    // prefetch first tile's chunk 0 (overlaps W staging)
    {
        const float* eb0 = e + (size_t)blockIdx.x * Vn * Hn;
#pragma unroll
        for (int i = 0; i < 8; i++) {
            int fid = i * 128 + gt;
            int row = fid >> 5, kq = fid & 31;
            cp_async16(dbase + (row * AS_STRIDE + kq * 4) * 4,
                       eb0 + (size_t)(g * 32 + row) * Hn + kq * 4);
        }
        asm volatile("cp.async.commit_group;\n");
    }

    // stage paired W ONCE (coalesced LDG over Cw[n][k])
    for (int i = t; i < Hn * Hn; i += 256) {
        int n = i >> 7, k = i & 127;
        WpU[(((k >> 3) * 4 + (k & 3)) * AS_STRIDE + n) * 2 + ((k >> 2) & 1)] = f2tf32(Cw[i]);
    }
    __syncthreads();    // W + zeroed reductions visible

    const int h4 = lane * 4;
    float4 sum4 = make_float4(0.f, 0.f, 0.f, 0.f);
    float4 sq4  = make_float4(0.f, 0.f, 0.f, 0.f);

    const uint32_t* AbufU = (const uint32_t*)As;
    const uint2* Wp2 = (const uint2*)sm;

    for (int p = blockIdx.x; p < NR; p += NPERS) {
        const int b = p >> 8;
        const float* ebase = e + (size_t)p * Vn * Hn;
        const float* AhB = g_Ah + (size_t)b * Vn * Hn;
        const float* VhB = g_Vh + (size_t)b * Vn * Hn;

        gsG[gt]       = graph[p * Vn + gt];
        gsG[gt + 128] = graph[p * Vn + gt + 128];

        float4 bias4;
        {
            float4 bb = *(const float4*)(g_Bh + (size_t)p * Hn + h4);
            float4 cb = *(const float4*)(Cb + h4);
            bias4 = make_float4(bb.x + cb.x, bb.y + cb.y, bb.z + cb.z, bb.w + cb.w);
        }
        float4 agg4 = make_float4(0.f, 0.f, 0.f, 0.f);

        for (int c = 0; c < 4; c++) {
            const int j0 = (c * 2 + g) * 32;
            asm volatile("cp.async.wait_group 0;\n" ::: "memory");
            asm volatile("bar.sync %0, 128;" :: "r"(barid) : "memory");

            // ---- GEMM: warp tile 32(j) x 32(h) over the 32-row chunk ----
            float cf[2][4][4];
#pragma unroll
            for (int rg = 0; rg < 2; rg++)
#pragma unroll
                for (int nt = 0; nt < 4; nt++)
#pragma unroll
                    for (int q = 0; q < 4; q++) cf[rg][nt][q] = 0.f;

#pragma unroll 2
            for (int ks = 0; ks < 16; ks++) {
                int k0 = ks * 8 + tig;
                uint32_t a[2][4];
#pragma unroll
                for (int rg = 0; rg < 2; rg++) {
                    int r = rg * 16 + gid;
                    a[rg][0] = AbufU[r * AS_STRIDE + k0];
                    a[rg][1] = AbufU[(r + 8) * AS_STRIDE + k0];
                    a[rg][2] = AbufU[r * AS_STRIDE + k0 + 4];
                    a[rg][3] = AbufU[(r + 8) * AS_STRIDE + k0 + 4];
                }
                uint2 bfr[4];
#pragma unroll
                for (int nt = 0; nt < 4; nt++)
                    bfr[nt] = Wp2[(ks * 4 + tig) * AS_STRIDE + wq * 32 + nt * 8 + gid];
#pragma unroll
                for (int rg = 0; rg < 2; rg++)
#pragma unroll
                    for (int nt = 0; nt < 4; nt++) {
                        asm volatile(
                            "mma.sync.aligned.m16n8k8.row.col.f32.tf32.tf32.f32 "
                            "{%0,%1,%2,%3},{%4,%5,%6,%7},{%8,%9},{%0,%1,%2,%3};"
                            : "+f"(cf[rg][nt][0]), "+f"(cf[rg][nt][1]),
                              "+f"(cf[rg][nt][2]), "+f"(cf[rg][nt][3])
                            : "r"(a[rg][0]), "r"(a[rg][1]), "r"(a[rg][2]), "r"(a[rg][3]),
                              "r"(bfr[nt].x), "r"(bfr[nt].y));
                    }
            }

            asm volatile("bar.sync %0, 128;" :: "r"(barid) : "memory");
            // ---- transpose fragments into the dead chunk buffer ----
#pragma unroll
            for (int rg = 0; rg < 2; rg++)
#pragma unroll
                for (int half = 0; half < 2; half++) {
                    int jl = rg * 16 + half * 8 + gid;
#pragma unroll
                    for (int nt = 0; nt < 4; nt++) {
                        int h = wq * 32 + nt * 8 + tig * 2;
                        *(float2*)(As + jl * AS_STRIDE + h) =
                            make_float2(cf[rg][nt][half * 2], cf[rg][nt][half * 2 + 1]);
                    }
                }
            asm volatile("bar.sync %0, 128;" :: "r"(barid) : "memory");

            // ---- coalesced epilogue: warp owns rows [wq*8, wq*8+8) ----
#pragma unroll
            for (int r = 0; r < 8; r++) {
                int jl = wq * 8 + r;
                int j  = j0 + jl;
                float4 cv = *(const float4*)(As + jl * AS_STRIDE + h4);
                float4 ah = *(const float4*)(AhB + (size_t)j * Hn + h4);
                float4 en;
                en.x = cv.x + ah.x + bias4.x;
                en.y = cv.y + ah.y + bias4.y;
                en.z = cv.z + ah.z + bias4.z;
                en.w = cv.w + ah.w + bias4.w;
                {
                    __half2 ha = __floats2half2_rn(en.x, en.y);
                    __half2 hb = __floats2half2_rn(en.z, en.w);
                    uint2 pk;
                    pk.x = *(uint32_t*)&ha;
                    pk.y = *(uint32_t*)&hb;
                    __stcs((uint2*)(g_enew + ((size_t)p * Vn + j) * Hn) + lane, pk);
                }
                sum4.x += en.x; sum4.y += en.y; sum4.z += en.z; sum4.w += en.w;
                sq4.x += en.x * en.x; sq4.y += en.y * en.y;
                sq4.z += en.z * en.z; sq4.w += en.w * en.w;
                if (!gsG[j]) {
                    float4 vh = *(const float4*)(VhB + (size_t)j * Hn + h4);
                    agg4.x += fast_sigmoid(en.x) * vh.x;
                    agg4.y += fast_sigmoid(en.y) * vh.y;
                    agg4.z += fast_sigmoid(en.z) * vh.z;
                    agg4.w += fast_sigmoid(en.w) * vh.w;
                }
            }
            asm volatile("bar.sync %0, 128;" :: "r"(barid) : "memory");

            // ---- prefetch: next chunk of this tile, or next tile's chunk 0 ----
            if (c < 3) {
                int jn = ((c + 1) * 2 + g) * 32;
#pragma unroll
                for (int i = 0; i < 8; i++) {
                    int fid = i * 128 + gt;
                    int row = fid >> 5, kq = fid & 31;
                    cp_async16(dbase + (row * AS_STRIDE + kq * 4) * 4,
                               ebase + (size_t)(jn + row) * Hn + kq * 4);
                }
                asm volatile("cp.async.commit_group;\n");
            } else if (p + NPERS < NR) {
                const float* ebn = e + (size_t)(p + NPERS) * Vn * Hn;
#pragma unroll
                for (int i = 0; i < 8; i++) {
                    int fid = i * 128 + gt;
                    int row = fid >> 5, kq = fid & 31;
                    cp_async16(dbase + (row * AS_STRIDE + kq * 4) * 4,
                               ebn + (size_t)(g * 32 + row) * Hn + kq * 4);
                }
                asm volatile("cp.async.commit_group;\n");
            }
        }

        // ---- per-tile gated-aggregation reduction (block-wide) ----
        __syncthreads();
        atomicAdd(&aggS[h4],     agg4.x);
        atomicAdd(&aggS[h4 + 1], agg4.y);
        atomicAdd(&aggS[h4 + 2], agg4.z);
        atomicAdd(&aggS[h4 + 3], agg4.w);
        __syncthreads();
        if (t < Hn) {
            g_hnew[(size_t)p * Hn + t] = g_Uh[(size_t)p * Hn + t] + aggS[t];
            aggS[t] = 0.f;
        }
    }

    // ---- final BN stats reduction (once per CTA) ----
    __syncthreads();
    atomicAdd(&sumS[h4],     sum4.x);
    atomicAdd(&sumS[h4 + 1], sum4.y);
    atomicAdd(&sumS[h4 + 2], sum4.z);
    atomicAdd(&sumS[h4 + 3], sum4.w);
    atomicAdd(&sqS[h4],      sq4.x);
    atomicAdd(&sqS[h4 + 1],  sq4.y);
    atomicAdd(&sqS[h4 + 2],  sq4.z);
    atomicAdd(&sqS[h4 + 3],  sq4.w);
    __syncthreads();
    if (t < Hn) {
        atomicAdd(&g_esum[t], sumS[t]);
        atomicAdd(&g_esq[t],  sqS[t]);
    }
}

// pass 2: h-side batchnorm in blocks 0..127 (scheduled FIRST so they overlap
// the stream), e normalize+relu+residual in blocks 128..65663.
__global__ void k_epass2(const float* __restrict__ ein,
                         float* __restrict__ eout,
                         const float* __restrict__ game,
                         const float* __restrict__ bete,
                         const float* __restrict__ hin,
                         const float* __restrict__ gamh,
                         const float* __restrict__ beth,
                         float* __restrict__ hout) {
    if (blockIdx.x >= 128) {
        __shared__ float scS[128], shS[128];
        int t = threadIdx.x;
        if (t < 128) {
            float mean = g_esum[t] * (1.0f / NE);
            float var  = g_esq[t] * (1.0f / NE) - mean * mean;
            float sc = game[t] * rsqrtf(var + 1e-5f);
            scS[t] = sc;
            shS[t] = bete[t] - mean * sc;
        }
        __syncthreads();
        size_t idx = (size_t)(blockIdx.x - 128) * blockDim.x + t;   // 4-channel unit
        int h0 = (int)((idx * 4) & 127);
        uint2 pk = __ldcs((const uint2*)g_enew + idx);
        __half2 ha = *(__half2*)&pk.x;
        __half2 hb = *(__half2*)&pk.y;
        float2 f01 = __half22float2(ha);
        float2 f23 = __half22float2(hb);
        float4 a = __ldcs((const float4*)ein + idx);
        float4 o;
        o.x = a.x + fmaxf(f01.x * scS[h0]     + shS[h0],     0.f);
        o.y = a.y + fmaxf(f01.y * scS[h0 + 1] + shS[h0 + 1], 0.f);
        o.z = a.z + fmaxf(f23.x * scS[h0 + 2] + shS[h0 + 2], 0.f);
        o.w = a.w + fmaxf(f23.y * scS[h0 + 3] + shS[h0 + 3], 0.f);
        ((float4*)eout)[idx] = o;
    } else {
        int h = blockIdx.x, t = threadIdx.x;
        float v[8];
        float s = 0.f, q = 0.f;
#pragma unroll
        for (int r = 0; r < 8; r++) {
            float x = g_hnew[(size_t)(t * 8 + r) * Hn + h];
            v[r] = x; s += x; q += x * x;
        }
        __shared__ float rs[256], rq[256];
        rs[t] = s; rq[t] = q; __syncthreads();
        for (int o = 128; o > 0; o >>= 1) {
            if (t < o) { rs[t] += rs[t + o]; rq[t] += rq[t + o]; }
            __syncthreads();
        }
        __shared__ float sc, sh;
        if (t == 0) {
            float mean = rs[0] * (1.0f / NR);
            float var  = rq[0] * (1.0f / NR) - mean * mean;
            float scale = gamh[h] * rsqrtf(var + 1e-5f);
            sc = scale; sh = beth[h] - mean * scale;
        }
        __syncthreads();
#pragma unroll
        for (int r = 0; r < 8; r++) {
            int row = t * 8 + r;
            float y = fmaxf(v[r] * sc + sh, 0.f);
            hout[(size_t)row * Hn + h] = hin[(size_t)row * Hn + h] + y;
        }
    }
}

// ---------------- launch ----------------
extern "C" void kernel_launch(void* const* d_in, const int* in_sizes, int n_in,
                              void* d_out, int out_size) {
    const float* h   = (const float*)d_in[0];
    const float* e   = (const float*)d_in[1];
    const int*   gra = (const int*)  d_in[2];
    const float* Uw  = (const float*)d_in[3],  *Ub = (const float*)d_in[4];
    const float* Vw  = (const float*)d_in[5],  *Vb = (const float*)d_in[6];
    const float* Aw  = (const float*)d_in[7],  *Ab = (const float*)d_in[8];
    const float* Bw  = (const float*)d_in[9],  *Bb = (const float*)d_in[10];
    const float* Cw  = (const float*)d_in[11], *Cb = (const float*)d_in[12];
    const float* gh  = (const float*)d_in[13], *bh = (const float*)d_in[14];
    const float* ge  = (const float*)d_in[15], *be = (const float*)d_in[16];

    float* out  = (float*)d_out;
    float* hout = out;                        // [2048,128]
    float* eout = out + (size_t)NR * Hn;      // [8,256,256,128]

    const int smemE = SMEM_FLOATS * 4;        // 104960 B -> 2 CTAs/SM
    cudaFuncSetAttribute(k_pass1, cudaFuncAttributeMaxDynamicSharedMemorySize, smemE);

    k_hlin4 <<<256, 256>>>(h, Uw, Ub, Vw, Vb, Aw, Ab, Bw, Bb);
    k_pass1 <<<NPERS, 256, smemE>>>(e, gra, Cw, Cb);
    k_epass2<<<65664, 256>>>(e, eout, ge, be, h, gh, bh, hout);
}

// round 16
// speedup vs baseline: 1.2223x; 1.0050x over previous
#include <cuda_runtime.h>
#include <cuda_fp16.h>
#include <math.h>
#include <stdint.h>

#define Bdim 8
#define Vn   256
#define Hn   128
#define NR   2048      /* B*V   */
#define NE   524288    /* B*V*V */
#define NPERS 304      /* persistent CTAs: 2 per SM on GB300 (152 SMs) */

// ---------------- device scratch (no allocation allowed) ----------------
__device__ float g_Uh[NR * Hn];
__device__ float g_Vh[NR * Hn];
__device__ float g_Ah[NR * Hn];
__device__ float g_Bh[NR * Hn];
__device__ float g_hnew[NR * Hn];
__device__ float g_esum[Hn];
__device__ float g_esq[Hn];
__device__ __half g_enew[(size_t)NE * Hn];   // 134 MB fp16 spill of e_new

// ---------------- helpers ----------------
__device__ __forceinline__ unsigned smem_u32(const void* p) {
    unsigned a;
    asm("{ .reg .u64 t; cvta.to.shared.u64 t, %1; cvt.u32.u64 %0, t; }"
        : "=r"(a) : "l"(p));
    return a;
}
__device__ __forceinline__ void cp_async16(unsigned dst, const void* src) {
    asm volatile("cp.async.cg.shared.global [%0], [%1], 16;\n" :: "r"(dst), "l"(src));
}
__device__ __forceinline__ uint32_t f2tf32(float f) {
    uint32_t u;
    asm("cvt.rna.tf32.f32 %0, %1;" : "=r"(u) : "f"(f));
    return u;
}
__device__ __forceinline__ float fast_sigmoid(float x) {
    float t;
    asm("tanh.approx.f32 %0, %1;" : "=f"(t) : "f"(0.5f * x));
    return 0.5f * t + 0.5f;
}

// ---------------- kernels ----------------

// h-linears: 256 blocks, each handles ONE weight array (which = blk>>6) for
// 32 rows. 4 rows x 4 cols per thread. Block 0 zeroes BN accumulators.
#define HL_STR 132
__global__ __launch_bounds__(256)
void k_hlin4(const float* __restrict__ h,
             const float* __restrict__ Uw, const float* __restrict__ Ub,
             const float* __restrict__ Vw, const float* __restrict__ Vb,
             const float* __restrict__ Aw, const float* __restrict__ Ab,
             const float* __restrict__ Bw, const float* __restrict__ Bb) {
    __shared__ float hs[32 * HL_STR];
    __shared__ float Ws[128 * HL_STR];
    const int t = threadIdx.x;
    const int lane = t & 31, wq = t >> 5;
    const int which = blockIdx.x >> 6;
    const int rbase = (blockIdx.x & 63) * 32;
    if (blockIdx.x == 0 && t < Hn) { g_esum[t] = 0.f; g_esq[t] = 0.f; }

#pragma unroll
    for (int i = 0; i < 4; i++) {
        int idx = i * 256 + t;
        int r = idx >> 5, kq = idx & 31;
        *(float4*)(hs + r * HL_STR + kq * 4) =
            *(const float4*)(h + (size_t)(rbase + r) * Hn + kq * 4);
    }

    const float* W; const float* bb; float* O;
    if      (which == 0) { W = Uw; bb = Ub; O = g_Uh; }
    else if (which == 1) { W = Vw; bb = Vb; O = g_Vh; }
    else if (which == 2) { W = Aw; bb = Ab; O = g_Ah; }
    else                 { W = Bw; bb = Bb; O = g_Bh; }

#pragma unroll
    for (int i = 0; i < 16; i++) {
        int idx = t + i * 256;
        int o = idx >> 5, kq = idx & 31;
        *(float4*)(Ws + o * HL_STR + kq * 4) = *(const float4*)(W + (size_t)o * Hn + kq * 4);
    }
    __syncthreads();

    float acc[4][4];
#pragma unroll
    for (int q = 0; q < 4; q++)
#pragma unroll
        for (int c = 0; c < 4; c++) acc[q][c] = 0.f;

#pragma unroll 4
    for (int k4 = 0; k4 < 32; k4++) {
        float4 hv[4];
#pragma unroll
        for (int q = 0; q < 4; q++)
            hv[q] = *(const float4*)(hs + (wq * 4 + q) * HL_STR + k4 * 4);
#pragma unroll
        for (int c = 0; c < 4; c++) {
            float4 w = *(const float4*)(Ws + (lane + 32 * c) * HL_STR + k4 * 4);
#pragma unroll
            for (int q = 0; q < 4; q++)
                acc[q][c] += hv[q].x * w.x + hv[q].y * w.y + hv[q].z * w.z + hv[q].w * w.w;
        }
    }
#pragma unroll
    for (int c = 0; c < 4; c++) {
        int col = lane + 32 * c;
        float bv = bb[col];
#pragma unroll
        for (int q = 0; q < 4; q++)
            O[(size_t)(rbase + wq * 4 + q) * Hn + col] = acc[q][c] + bv;
    }
}

// Pass 1: PERSISTENT tf32 mma.sync GEMM + coalesced fused epilogue.
// NPERS CTAs (2/SM), W tile staged ONCE per CTA; 2 independent 4-warp groups,
// 32-row chunks, cross-tile cp.async prefetch. e_new spilled fp16.
#define AS_STRIDE 132
#define WP_FLOATS 16896               /* 64*132 float2 */
#define BUF_FLOATS 4224               /* 32*132 */
#define BUF_OFF   16896
#define GS_OFF    25344               /* 2 x 256 ints (per-group graph row) */
#define AGG_OFF   25856
#define SUM_OFF   25984
#define SQ_OFF    26112
#define SMEM_FLOATS 26240             /* 104960 B -> 2 CTAs/SM */

__global__ __launch_bounds__(256, 2)
void k_pass1(const float* __restrict__ e,
             const int* __restrict__ graph,
             const float* __restrict__ Cw,
             const float* __restrict__ Cb) {
    extern __shared__ float sm[];
    uint32_t* WpU = (uint32_t*)sm;

    const int t = threadIdx.x;
    const int lane = t & 31, wid = t >> 5;
    const int g  = wid >> 2;
    const int wq = wid & 3;
    const int gid = lane >> 2, tig = lane & 3;
    const int barid = g + 1;
    const int gt = t & 127;

    int*   gsG  = (int*)(sm + GS_OFF) + g * 256;
    float* aggS = sm + AGG_OFF;
    float* sumS = sm + SUM_OFF;
    float* sqS  = sm + SQ_OFF;

    float* As = sm + BUF_OFF + g * BUF_FLOATS;
    const unsigned dbase = smem_u32(As);

    if (t < 128) { aggS[t] = 0.f; sumS[t] = 0.f; sqS[t] = 0.f; }

    // prefetch first tile's chunk 0 (overlaps W staging)
    if (blockIdx.x < NR) {
        const float* eb0 = e + (size_t)blockIdx.x * Vn * Hn;
#pragma unroll
        for (int i = 0; i < 8; i++) {
            int fid = i * 128 + gt;
            int row = fid >> 5, kq = fid & 31;
            cp_async16(dbase + (row * AS_STRIDE + kq * 4) * 4,
                       eb0 + (size_t)(g * 32 + row) * Hn + kq * 4);
        }
        asm volatile("cp.async.commit_group;\n");
    }

    // stage paired W ONCE
    for (int i = t; i < Hn * Hn; i += 256) {
        int n = i >> 7, k = i & 127;
        WpU[(((k >> 3) * 4 + (k & 3)) * AS_STRIDE + n) * 2 + ((k >> 2) & 1)] = f2tf32(Cw[i]);
    }
    __syncthreads();

    const int h4 = lane * 4;
    float4 sum4 = make_float4(0.f, 0.f, 0.f, 0.f);
    float4 sq4  = make_float4(0.f, 0.f, 0.f, 0.f);

    const uint32_t* AbufU = (const uint32_t*)As;
    const uint2* Wp2 = (const uint2*)sm;

    for (int p = blockIdx.x; p < NR; p += NPERS) {
        const int b = p >> 8;
        const float* ebase = e + (size_t)p * Vn * Hn;
        const float* AhB = g_Ah + (size_t)b * Vn * Hn;
        const float* VhB = g_Vh + (size_t)b * Vn * Hn;

        gsG[gt]       = graph[p * Vn + gt];
        gsG[gt + 128] = graph[p * Vn + gt + 128];

        float4 bias4;
        {
            float4 bb = *(const float4*)(g_Bh + (size_t)p * Hn + h4);
            float4 cb = *(const float4*)(Cb + h4);
            bias4 = make_float4(bb.x + cb.x, bb.y + cb.y, bb.z + cb.z, bb.w + cb.w);
        }
        float4 agg4 = make_float4(0.f, 0.f, 0.f, 0.f);

        for (int c = 0; c < 4; c++) {
            const int j0 = (c * 2 + g) * 32;
            asm volatile("cp.async.wait_group 0;\n" ::: "memory");
            asm volatile("bar.sync %0, 128;" :: "r"(barid) : "memory");

            float cf[2][4][4];
#pragma unroll
            for (int rg = 0; rg < 2; rg++)
#pragma unroll
                for (int nt = 0; nt < 4; nt++)
#pragma unroll
                    for (int q = 0; q < 4; q++) cf[rg][nt][q] = 0.f;

#pragma unroll 2
            for (int ks = 0; ks < 16; ks++) {
                int k0 = ks * 8 + tig;
                uint32_t a[2][4];
#pragma unroll
                for (int rg = 0; rg < 2; rg++) {
                    int r = rg * 16 + gid;
                    a[rg][0] = AbufU[r * AS_STRIDE + k0];
                    a[rg][1] = AbufU[(r + 8) * AS_STRIDE + k0];
                    a[rg][2] = AbufU[r * AS_STRIDE + k0 + 4];
                    a[rg][3] = AbufU[(r + 8) * AS_STRIDE + k0 + 4];
                }
                uint2 bfr[4];
#pragma unroll
                for (int nt = 0; nt < 4; nt++)
                    bfr[nt] = Wp2[(ks * 4 + tig) * AS_STRIDE + wq * 32 + nt * 8 + gid];
#pragma unroll
                for (int rg = 0; rg < 2; rg++)
#pragma unroll
                    for (int nt = 0; nt < 4; nt++) {
                        asm volatile(
                            "mma.sync.aligned.m16n8k8.row.col.f32.tf32.tf32.f32 "
                            "{%0,%1,%2,%3},{%4,%5,%6,%7},{%8,%9},{%0,%1,%2,%3};"
                            : "+f"(cf[rg][nt][0]), "+f"(cf[rg][nt][1]),
                              "+f"(cf[rg][nt][2]), "+f"(cf[rg][nt][3])
                            : "r"(a[rg][0]), "r"(a[rg][1]), "r"(a[rg][2]), "r"(a[rg][3]),
                              "r"(bfr[nt].x), "r"(bfr[nt].y));
                    }
            }

            asm volatile("bar.sync %0, 128;" :: "r"(barid) : "memory");
#pragma unroll
            for (int rg = 0; rg < 2; rg++)
#pragma unroll
                for (int half = 0; half < 2; half++) {
                    int jl = rg * 16 + half * 8 + gid;
#pragma unroll
                    for (int nt = 0; nt < 4; nt++) {
                        int h = wq * 32 + nt * 8 + tig * 2;
                        *(float2*)(As + jl * AS_STRIDE + h) =
                            make_float2(cf[rg][nt][half * 2], cf[rg][nt][half * 2 + 1]);
                    }
                }
            asm volatile("bar.sync %0, 128;" :: "r"(barid) : "memory");

#pragma unroll
            for (int r = 0; r < 8; r++) {
                int jl = wq * 8 + r;
                int j  = j0 + jl;
                float4 cv = *(const float4*)(As + jl * AS_STRIDE + h4);
                float4 ah = *(const float4*)(AhB + (size_t)j * Hn + h4);
                float4 en;
                en.x = cv.x + ah.x + bias4.x;
                en.y = cv.y + ah.y + bias4.y;
                en.z = cv.z + ah.z + bias4.z;
                en.w = cv.w + ah.w + bias4.w;
                {
                    __half2 ha = __floats2half2_rn(en.x, en.y);
                    __half2 hb = __floats2half2_rn(en.z, en.w);
                    uint2 pk;
                    pk.x = *(uint32_t*)&ha;
                    pk.y = *(uint32_t*)&hb;
                    __stcs((uint2*)(g_enew + ((size_t)p * Vn + j) * Hn) + lane, pk);
                }
                sum4.x += en.x; sum4.y += en.y; sum4.z += en.z; sum4.w += en.w;
                sq4.x += en.x * en.x; sq4.y += en.y * en.y;
                sq4.z += en.z * en.z; sq4.w += en.w * en.w;
                if (!gsG[j]) {
                    float4 vh = *(const float4*)(VhB + (size_t)j * Hn + h4);
                    agg4.x += fast_sigmoid(en.x) * vh.x;
                    agg4.y += fast_sigmoid(en.y) * vh.y;
                    agg4.z += fast_sigmoid(en.z) * vh.z;
                    agg4.w += fast_sigmoid(en.w) * vh.w;
                }
            }
            asm volatile("bar.sync %0, 128;" :: "r"(barid) : "memory");

            if (c < 3) {
                int jn = ((c + 1) * 2 + g) * 32;
#pragma unroll
                for (int i = 0; i < 8; i++) {
                    int fid = i * 128 + gt;
                    int row = fid >> 5, kq = fid & 31;
                    cp_async16(dbase + (row * AS_STRIDE + kq * 4) * 4,
                               ebase + (size_t)(jn + row) * Hn + kq * 4);
                }
                asm volatile("cp.async.commit_group;\n");
            } else if (p + NPERS < NR) {
                const float* ebn = e + (size_t)(p + NPERS) * Vn * Hn;
#pragma unroll
                for (int i = 0; i < 8; i++) {
                    int fid = i * 128 + gt;
                    int row = fid >> 5, kq = fid & 31;
                    cp_async16(dbase + (row * AS_STRIDE + kq * 4) * 4,
                               ebn + (size_t)(g * 32 + row) * Hn + kq * 4);
                }
                asm volatile("cp.async.commit_group;\n");
            }
        }

        __syncthreads();
        atomicAdd(&aggS[h4],     agg4.x);
        atomicAdd(&aggS[h4 + 1], agg4.y);
        atomicAdd(&aggS[h4 + 2], agg4.z);
        atomicAdd(&aggS[h4 + 3], agg4.w);
        __syncthreads();
        if (t < Hn) {
            g_hnew[(size_t)p * Hn + t] = g_Uh[(size_t)p * Hn + t] + aggS[t];
            aggS[t] = 0.f;
        }
    }

    __syncthreads();
    atomicAdd(&sumS[h4],     sum4.x);
    atomicAdd(&sumS[h4 + 1], sum4.y);
    atomicAdd(&sumS[h4 + 2], sum4.z);
    atomicAdd(&sumS[h4 + 3], sum4.w);
    atomicAdd(&sqS[h4],      sq4.x);
    atomicAdd(&sqS[h4 + 1],  sq4.y);
    atomicAdd(&sqS[h4 + 2],  sq4.z);
    atomicAdd(&sqS[h4 + 3],  sq4.w);
    __syncthreads();
    if (t < Hn) {
        atomicAdd(&g_esum[t], sumS[t]);
        atomicAdd(&g_esq[t],  sqS[t]);
    }
}

// pass 2: h-side batchnorm in blocks 0..127 (scheduled first), e
// normalize+relu+residual in blocks 128..32895, TWO stream units per thread.
__global__ void k_epass2(const float* __restrict__ ein,
                         float* __restrict__ eout,
                         const float* __restrict__ game,
                         const float* __restrict__ bete,
                         const float* __restrict__ hin,
                         const float* __restrict__ gamh,
                         const float* __restrict__ beth,
                         float* __restrict__ hout) {
    if (blockIdx.x >= 128) {
        __shared__ float scS[128], shS[128];
        int t = threadIdx.x;
        if (t < 128) {
            float mean = g_esum[t] * (1.0f / NE);
            float var  = g_esq[t] * (1.0f / NE) - mean * mean;
            float sc = game[t] * rsqrtf(var + 1e-5f);
            scS[t] = sc;
            shS[t] = bete[t] - mean * sc;
        }
        __syncthreads();
        size_t base = ((size_t)(blockIdx.x - 128) * blockDim.x) * 2 + t;  // unit idx
#pragma unroll
        for (int u = 0; u < 2; u++) {
            size_t idx = base + (size_t)u * blockDim.x;
            int h0 = (int)((idx * 4) & 127);
            uint2 pk = __ldcs((const uint2*)g_enew + idx);
            __half2 ha = *(__half2*)&pk.x;
            __half2 hb = *(__half2*)&pk.y;
            float2 f01 = __half22float2(ha);
            float2 f23 = __half22float2(hb);
            float4 a = __ldcs((const float4*)ein + idx);
            float4 o;
            o.x = a.x + fmaxf(f01.x * scS[h0]     + shS[h0],     0.f);
            o.y = a.y + fmaxf(f01.y * scS[h0 + 1] + shS[h0 + 1], 0.f);
            o.z = a.z + fmaxf(f23.x * scS[h0 + 2] + shS[h0 + 2], 0.f);
            o.w = a.w + fmaxf(f23.y * scS[h0 + 3] + shS[h0 + 3], 0.f);
            ((float4*)eout)[idx] = o;
        }
    } else {
        int h = blockIdx.x, t = threadIdx.x;
        float v[8];
        float s = 0.f, q = 0.f;
#pragma unroll
        for (int r = 0; r < 8; r++) {
            float x = g_hnew[(size_t)(t * 8 + r) * Hn + h];
            v[r] = x; s += x; q += x * x;
        }
        __shared__ float rs[256], rq[256];
        rs[t] = s; rq[t] = q; __syncthreads();
        for (int o = 128; o > 0; o >>= 1) {
            if (t < o) { rs[t] += rs[t + o]; rq[t] += rq[t + o]; }
            __syncthreads();
        }
        __shared__ float sc, sh;
        if (t == 0) {
            float mean = rs[0] * (1.0f / NR);
            float var  = rq[0] * (1.0f / NR) - mean * mean;
            float scale = gamh[h] * rsqrtf(var + 1e-5f);
            sc = scale; sh = beth[h] - mean * scale;
        }
        __syncthreads();
#pragma unroll
        for (int r = 0; r < 8; r++) {
            int row = t * 8 + r;
            float y = fmaxf(v[r] * sc + sh, 0.f);
            hout[(size_t)row * Hn + h] = hin[(size_t)row * Hn + h] + y;
        }
    }
}

// ---------------- launch ----------------
extern "C" void kernel_launch(void* const* d_in, const int* in_sizes, int n_in,
                              void* d_out, int out_size) {
    const float* h   = (const float*)d_in[0];
    const float* e   = (const float*)d_in[1];
    const int*   gra = (const int*)  d_in[2];
    const float* Uw  = (const float*)d_in[3],  *Ub = (const float*)d_in[4];
    const float* Vw  = (const float*)d_in[5],  *Vb = (const float*)d_in[6];
    const float* Aw  = (const float*)d_in[7],  *Ab = (const float*)d_in[8];
    const float* Bw  = (const float*)d_in[9],  *Bb = (const float*)d_in[10];
    const float* Cw  = (const float*)d_in[11], *Cb = (const float*)d_in[12];
    const float* gh  = (const float*)d_in[13], *bh = (const float*)d_in[14];
    const float* ge  = (const float*)d_in[15], *be = (const float*)d_in[16];

    float* out  = (float*)d_out;
    float* hout = out;                        // [2048,128]
    float* eout = out + (size_t)NR * Hn;      // [8,256,256,128]

    const int smemE = SMEM_FLOATS * 4;        // 104960 B -> 2 CTAs/SM
    cudaFuncSetAttribute(k_pass1, cudaFuncAttributeMaxDynamicSharedMemorySize, smemE);

    k_hlin4 <<<256, 256>>>(h, Uw, Ub, Vw, Vb, Aw, Ab, Bw, Bb);
    k_pass1 <<<NPERS, 256, smemE>>>(e, gra, Cw, Cb);
    k_epass2<<<32896, 256>>>(e, eout, ge, be, h, gh, bh, hout);
}